// round 15
// baseline (speedup 1.0000x reference)
#include <cuda_runtime.h>
#include <cuda_fp16.h>
#include <cstdint>

#define B_    16
#define CIN_  64
#define COUT_ 64
#define HH    256
#define WW    256
#define HW    (HH * WW)
#define EPSF  1e-8f

// Demodulated fp16 weights in exact m16n8k16-B fragment-consumption order:
// [b][tap 0..8][q 0..3][coh 0..1][sub 0..1][lane 0..31][4 x b32 words]
__device__ __align__(16) __half g_wt[B_ * 9 * 4 * 2 * 2 * 32 * 8];

__device__ __forceinline__ uint32_t pack_h2(float lo, float hi) {
    uint32_t r;
    asm("cvt.rn.f16x2.f32 %0, %1, %2;" : "=r"(r) : "f"(hi), "f"(lo));
    return r;
}
__device__ __forceinline__ void stg_cs(float* p, float v) {
    asm volatile("st.global.cs.f32 [%0], %1;" :: "l"(p), "f"(v) : "memory");
}

#define MMA_F16(d, a, b0, b1)                                                 \
    asm volatile(                                                             \
        "mma.sync.aligned.m16n8k16.row.col.f32.f16.f16.f32 "                  \
        "{%0,%1,%2,%3},{%4,%5,%6,%7},{%8,%9},{%0,%1,%2,%3};"                  \
        : "+f"((d)[0]), "+f"((d)[1]), "+f"((d)[2]), "+f"((d)[3])              \
        : "r"((a)[0]), "r"((a)[1]), "r"((a)[2]), "r"((a)[3]),                 \
          "r"(b0), "r"(b1))

// ---------------------------------------------------------------------------
// Kernel 1: modulate + demodulate + fp16-round + swizzle into fragment order
// grid (COUT, B), block CIN.  (validated layout)
// ---------------------------------------------------------------------------
__global__ void modw_kernel(const float* __restrict__ w,
                            const float* __restrict__ y,
                            __half* __restrict__ wt) {
    const int co = blockIdx.x;
    const int b  = blockIdx.y;
    const int ci = threadIdx.x;

    const float c  = 1.0f / 24.0f;               // (64*9)^-0.5
    const float yv = y[b * CIN_ + ci] * c;

    float v[9];
    float s = 0.0f;
    const float* wp = w + (co * CIN_ + ci) * 9;
#pragma unroll
    for (int t = 0; t < 9; t++) {
        v[t] = wp[t] * yv;
        s += v[t] * v[t];
    }
#pragma unroll
    for (int off = 16; off > 0; off >>= 1)
        s += __shfl_down_sync(0xffffffffu, s, off);
    __shared__ float ps[2];
    if ((ci & 31) == 0) ps[ci >> 5] = s;
    __syncthreads();
    const float d = rsqrtf(ps[0] + ps[1] + EPSF);

    const int q      = ci >> 4;                  // k16 chunk
    const int k      = ci & 15;
    const int reg    = (k >> 3) & 1;
    const int lane   = (co & 7) * 4 + ((k & 7) >> 1);
    const int hsel   = k & 1;
    const int j      = (co >> 3) & 3;            // n-tile
    const int sub    = j >> 1;
    const int word   = (j & 1) * 2 + reg;
    const int coh    = co >> 5;

#pragma unroll
    for (int t = 0; t < 9; t++) {
        const size_t idx =
            (((((((size_t)(b * 9 + t) * 4 + q) * 2 + coh) * 2 + sub)
               * 32 + lane) * 4 + word) * 2) + hsel;
        wt[idx] = __float2half_rn(v[t] * d);
    }
}

// ---------------------------------------------------------------------------
// Kernel 2: fp16 mma.sync (m16n8k16) implicit-GEMM conv, M64 x N32 warp tile.
// CTA: 128 px (2h x 64w) x 64 co, 128 threads, 4 warps (pxg = wid&1, coh = wid>>1).
// X layout (plane-PAIR interleaved, LDS.64):
//   word addr = q*2208 + pq*552 + r*136 + 2 + 2*c + s   (conflict-free)
// A fragment: 8 LDS.64 per q-step. Staging: LDG.128 + STS.128 (interior).
// B from gmem (fragment order, rolling LDG.128).
// OCC 5 (__launch_bounds__(128,5), reg cap 102) + streaming output stores.
// ---------------------------------------------------------------------------
#define RS_   136
#define PPS_  552
#define QS_   2208
#define XS_W32   (4 * QS_)           // 8832 words = 35.3 KB
#define DYN_SMEM (XS_W32 * 4)

__global__ void __launch_bounds__(128, 5)
conv_mma_kernel(const float* __restrict__ X,
                const __half* __restrict__ wt,
                float* __restrict__ out) {
    extern __shared__ __align__(16) uint32_t xs32[];

    const int tid  = threadIdx.x;
    const int lane = tid & 31;
    const int wid  = tid >> 5;
    const int coh  = wid >> 1;           // co half (0/1)
    const int pxg  = wid & 1;            // h-row within tile (0/1)

    const int b  = blockIdx.z;
    const int h0 = blockIdx.y * 2;
    const int w0 = blockIdx.x * 64;

    const float* Xb = X + (size_t)b * CIN_ * HW;
    const uint4* bp = (const uint4*)(wt) + (size_t)b * 4608 + coh * 64 + lane;

    float acc[4][4][4];
#pragma unroll
    for (int mt = 0; mt < 4; mt++)
#pragma unroll
        for (int nt = 0; nt < 4; nt++)
#pragma unroll
            for (int qq = 0; qq < 4; qq++) acc[mt][nt][qq] = 0.0f;

    // ---- stage X tile: interior cols via LDG.128 + STS.128 ----
    {
        const int grp = tid >> 3;        // 0..15: (q, pq)
        const int l8  = tid & 7;
        const int q   = grp >> 2;
        const int pq  = grp & 3;
        const int ci0 = 16 * q + 2 * pq;           // s0 planes ci0, ci0+1
        const float* xp0 = Xb + (size_t)ci0 * HW + (w0 - 1);
        uint32_t* dst = xs32 + q * QS_ + pq * PPS_;

#pragma unroll
        for (int r = 0; r < 4; r++) {
            const int gh = h0 - 1 + r;
            const bool hok = (unsigned)gh < (unsigned)HH;
            const float* row0 = xp0 + gh * WW;
            uint32_t* drow = dst + r * RS_;
#pragma unroll
            for (int j = 0; j < 2; j++) {
                const int c0 = 1 + 4 * (l8 + 8 * j);   // 1..61, gmem 16B-aligned
                float4 v0 = make_float4(0.f, 0.f, 0.f, 0.f);
                float4 v1 = v0, v2 = v0, v3 = v0;
                if (hok) {
                    v0 = *(const float4*)(row0 + c0);
                    v1 = *(const float4*)(row0 + HW + c0);
                    v2 = *(const float4*)(row0 + 8 * HW + c0);
                    v3 = *(const float4*)(row0 + 9 * HW + c0);
                }
                uint4 o0, o1;
                o0.x = pack_h2(v0.x, v1.x); o0.y = pack_h2(v2.x, v3.x);
                o0.z = pack_h2(v0.y, v1.y); o0.w = pack_h2(v2.y, v3.y);
                o1.x = pack_h2(v0.z, v1.z); o1.y = pack_h2(v2.z, v3.z);
                o1.z = pack_h2(v0.w, v1.w); o1.w = pack_h2(v2.w, v3.w);
                *(uint4*)(drow + 2 + 2 * c0)     = o0;   // smem 16B-aligned
                *(uint4*)(drow + 2 + 2 * c0 + 4) = o1;
            }
        }

        // edge columns c in {0, 65}: 2 words per thread
#pragma unroll
        for (int e = 0; e < 2; e++) {
            const int wd  = tid * 2 + e;
            const int ce  = wd & 1;
            const int s   = (wd >> 1) & 1;
            const int r   = (wd >> 2) & 3;
            const int pq2 = (wd >> 4) & 3;
            const int q2  = (wd >> 6) & 3;
            const int cia = 16 * q2 + 8 * s + 2 * pq2;
            const int gh  = h0 - 1 + r;
            const int gw  = w0 - 1 + (ce ? 65 : 0);
            float u0 = 0.f, u1 = 0.f;
            if (((unsigned)gh < (unsigned)HH) && ((unsigned)gw < (unsigned)WW)) {
                u0 = __ldg(Xb + (size_t)cia * HW + gh * WW + gw);
                u1 = __ldg(Xb + (size_t)(cia + 1) * HW + gh * WW + gw);
            }
            xs32[q2 * QS_ + pq2 * PPS_ + r * RS_ + 2 + 130 * ce + s] =
                pack_h2(u0, u1);
        }
    }
    __syncthreads();

    // per-warp A base (uint2 units): pq = lane&3, col = lane>>2, row = pxg
    const uint2* xw2 = (const uint2*)xs32 + (size_t)(lane & 3) * (PPS_ / 2)
                     + pxg * (RS_ / 2) + 1 + (lane >> 2);

#pragma unroll 1
    for (int kh = 0; kh < 3; kh++) {
#pragma unroll 1
        for (int kw = 0; kw < 3; kw++) {
            const uint2* abase = xw2 + kh * (RS_ / 2) + kw;

#pragma unroll
            for (int q = 0; q < 4; q++) {        // k16 chunk
                const uint4 bs0 = __ldg(bp);          // n-tiles 0,1
                const uint4 bs1 = __ldg(bp + 32);     // n-tiles 2,3
                bp += 128;

                const uint2* ap = abase + (size_t)q * (QS_ / 2);
                uint32_t a[4][4];
#pragma unroll
                for (int mt = 0; mt < 4; mt++) {
                    const uint2 lo = ap[mt * 16];        // (a0, a2)
                    const uint2 hi = ap[mt * 16 + 8];    // (a1, a3)
                    a[mt][0] = lo.x; a[mt][1] = hi.x;
                    a[mt][2] = lo.y; a[mt][3] = hi.y;
                }

#pragma unroll
                for (int mt = 0; mt < 4; mt++) {
                    MMA_F16(acc[mt][0], a[mt], bs0.x, bs0.y);
                    MMA_F16(acc[mt][1], a[mt], bs0.z, bs0.w);
                    MMA_F16(acc[mt][2], a[mt], bs1.x, bs1.y);
                    MMA_F16(acc[mt][3], a[mt], bs1.z, bs1.w);
                }
            }
        }
    }

    // ---- epilogue: streaming stores (evict-first; output is write-once) ----
    const int co0 = coh * 32;
    const int h   = h0 + pxg;
#pragma unroll
    for (int mt = 0; mt < 4; mt++) {
        const int wcol = w0 + mt * 16 + (lane >> 2);
        float* o0 = out + (size_t)b * COUT_ * HW + (size_t)h * WW + wcol;
#pragma unroll
        for (int nt = 0; nt < 4; nt++) {
            const int co = co0 + nt * 8 + 2 * (lane & 3);
            float* p = o0 + (size_t)co * HW;
            stg_cs(p,          acc[mt][nt][0]);   // (px,    co)
            stg_cs(p + HW,     acc[mt][nt][1]);   // (px,    co+1)
            stg_cs(p + 8,      acc[mt][nt][2]);   // (px+8,  co)
            stg_cs(p + HW + 8, acc[mt][nt][3]);   // (px+8,  co+1)
        }
    }
}

// ---------------------------------------------------------------------------
extern "C" void kernel_launch(void* const* d_in, const int* in_sizes, int n_in,
                              void* d_out, int out_size) {
    const float* X = (const float*)d_in[0];      // (16,64,256,256)
    const float* y = (const float*)d_in[1];      // (16,64)
    const float* w = (const float*)d_in[2];      // (64,64,3,3)
    float* out = (float*)d_out;                  // (16,64,256,256)

    __half* wt;
    cudaGetSymbolAddress((void**)&wt, g_wt);

    cudaFuncSetAttribute(conv_mma_kernel,
                         cudaFuncAttributeMaxDynamicSharedMemorySize, DYN_SMEM);

    modw_kernel<<<dim3(COUT_, B_), CIN_>>>(w, y, wt);

    dim3 grid(WW / 64, HH / 2, B_);
    conv_mma_kernel<<<grid, 128, DYN_SMEM>>>(X, wt, out);
}

// round 16
// speedup vs baseline: 1.1509x; 1.1509x over previous
#include <cuda_runtime.h>
#include <cuda_fp16.h>
#include <cstdint>

#define B_    16
#define CIN_  64
#define COUT_ 64
#define HH    256
#define WW    256
#define HW    (HH * WW)
#define EPSF  1e-8f

// Demodulated fp16 weights in exact m16n8k16-B fragment-consumption order:
// [b][tap 0..8][q 0..3][coh 0..1][sub 0..1][lane 0..31][4 x b32 words]
__device__ __align__(16) __half g_wt[B_ * 9 * 4 * 2 * 2 * 32 * 8];

__device__ __forceinline__ uint32_t pack_h2(float lo, float hi) {
    uint32_t r;
    asm("cvt.rn.f16x2.f32 %0, %1, %2;" : "=r"(r) : "f"(hi), "f"(lo));
    return r;
}
__device__ __forceinline__ void stg_cs(float* p, float v) {
    asm volatile("st.global.cs.f32 [%0], %1;" :: "l"(p), "f"(v) : "memory");
}

#define MMA_F16(d, a, b0, b1)                                                 \
    asm volatile(                                                             \
        "mma.sync.aligned.m16n8k16.row.col.f32.f16.f16.f32 "                  \
        "{%0,%1,%2,%3},{%4,%5,%6,%7},{%8,%9},{%0,%1,%2,%3};"                  \
        : "+f"((d)[0]), "+f"((d)[1]), "+f"((d)[2]), "+f"((d)[3])              \
        : "r"((a)[0]), "r"((a)[1]), "r"((a)[2]), "r"((a)[3]),                 \
          "r"(b0), "r"(b1))

// ---------------------------------------------------------------------------
// Kernel 1: modulate + demodulate + fp16-round + swizzle into fragment order
// grid (COUT, B), block CIN.  (validated layout)
// ---------------------------------------------------------------------------
__global__ void modw_kernel(const float* __restrict__ w,
                            const float* __restrict__ y,
                            __half* __restrict__ wt) {
    const int co = blockIdx.x;
    const int b  = blockIdx.y;
    const int ci = threadIdx.x;

    const float c  = 1.0f / 24.0f;               // (64*9)^-0.5
    const float yv = y[b * CIN_ + ci] * c;

    float v[9];
    float s = 0.0f;
    const float* wp = w + (co * CIN_ + ci) * 9;
#pragma unroll
    for (int t = 0; t < 9; t++) {
        v[t] = wp[t] * yv;
        s += v[t] * v[t];
    }
#pragma unroll
    for (int off = 16; off > 0; off >>= 1)
        s += __shfl_down_sync(0xffffffffu, s, off);
    __shared__ float ps[2];
    if ((ci & 31) == 0) ps[ci >> 5] = s;
    __syncthreads();
    const float d = rsqrtf(ps[0] + ps[1] + EPSF);

    const int q      = ci >> 4;                  // k16 chunk
    const int k      = ci & 15;
    const int reg    = (k >> 3) & 1;
    const int lane   = (co & 7) * 4 + ((k & 7) >> 1);
    const int hsel   = k & 1;
    const int j      = (co >> 3) & 3;            // n-tile
    const int sub    = j >> 1;
    const int word   = (j & 1) * 2 + reg;
    const int coh    = co >> 5;

#pragma unroll
    for (int t = 0; t < 9; t++) {
        const size_t idx =
            (((((((size_t)(b * 9 + t) * 4 + q) * 2 + coh) * 2 + sub)
               * 32 + lane) * 4 + word) * 2) + hsel;
        wt[idx] = __float2half_rn(v[t] * d);
    }
}

// ---------------------------------------------------------------------------
// Kernel 2: fp16 mma.sync (m16n8k16) implicit-GEMM conv, M64 x N32 warp tile.
// EXACT R14 structure (234.6us, occ 4 via __launch_bounds__(128,4), regs 128),
// single delta: epilogue uses st.global.cs (evict-first streaming stores) to
// keep the write-once 64MB output from sweeping B-fragment slabs out of L2.
// ---------------------------------------------------------------------------
#define RS_   136
#define PPS_  552
#define QS_   2208
#define XS_W32   (4 * QS_)           // 8832 words = 35.3 KB
#define DYN_SMEM (XS_W32 * 4)

__global__ void __launch_bounds__(128, 4)
conv_mma_kernel(const float* __restrict__ X,
                const __half* __restrict__ wt,
                float* __restrict__ out) {
    extern __shared__ __align__(16) uint32_t xs32[];

    const int tid  = threadIdx.x;
    const int lane = tid & 31;
    const int wid  = tid >> 5;
    const int coh  = wid >> 1;           // co half (0/1)
    const int pxg  = wid & 1;            // h-row within tile (0/1)

    const int b  = blockIdx.z;
    const int h0 = blockIdx.y * 2;
    const int w0 = blockIdx.x * 64;

    const float* Xb = X + (size_t)b * CIN_ * HW;
    const uint4* bp = (const uint4*)(wt) + (size_t)b * 4608 + coh * 64 + lane;

    float acc[4][4][4];
#pragma unroll
    for (int mt = 0; mt < 4; mt++)
#pragma unroll
        for (int nt = 0; nt < 4; nt++)
#pragma unroll
            for (int qq = 0; qq < 4; qq++) acc[mt][nt][qq] = 0.0f;

    // ---- stage X tile: interior cols via LDG.128 + STS.128 ----
    {
        const int grp = tid >> 3;        // 0..15: (q, pq)
        const int l8  = tid & 7;
        const int q   = grp >> 2;
        const int pq  = grp & 3;
        const int ci0 = 16 * q + 2 * pq;           // s0 planes ci0, ci0+1
        const float* xp0 = Xb + (size_t)ci0 * HW + (w0 - 1);
        uint32_t* dst = xs32 + q * QS_ + pq * PPS_;

#pragma unroll
        for (int r = 0; r < 4; r++) {
            const int gh = h0 - 1 + r;
            const bool hok = (unsigned)gh < (unsigned)HH;
            const float* row0 = xp0 + gh * WW;
            uint32_t* drow = dst + r * RS_;
#pragma unroll
            for (int j = 0; j < 2; j++) {
                const int c0 = 1 + 4 * (l8 + 8 * j);   // 1..61, gmem 16B-aligned
                float4 v0 = make_float4(0.f, 0.f, 0.f, 0.f);
                float4 v1 = v0, v2 = v0, v3 = v0;
                if (hok) {
                    v0 = *(const float4*)(row0 + c0);
                    v1 = *(const float4*)(row0 + HW + c0);
                    v2 = *(const float4*)(row0 + 8 * HW + c0);
                    v3 = *(const float4*)(row0 + 9 * HW + c0);
                }
                uint4 o0, o1;
                o0.x = pack_h2(v0.x, v1.x); o0.y = pack_h2(v2.x, v3.x);
                o0.z = pack_h2(v0.y, v1.y); o0.w = pack_h2(v2.y, v3.y);
                o1.x = pack_h2(v0.z, v1.z); o1.y = pack_h2(v2.z, v3.z);
                o1.z = pack_h2(v0.w, v1.w); o1.w = pack_h2(v2.w, v3.w);
                *(uint4*)(drow + 2 + 2 * c0)     = o0;   // smem 16B-aligned
                *(uint4*)(drow + 2 + 2 * c0 + 4) = o1;
            }
        }

        // edge columns c in {0, 65}: 2 words per thread
#pragma unroll
        for (int e = 0; e < 2; e++) {
            const int wd  = tid * 2 + e;
            const int ce  = wd & 1;
            const int s   = (wd >> 1) & 1;
            const int r   = (wd >> 2) & 3;
            const int pq2 = (wd >> 4) & 3;
            const int q2  = (wd >> 6) & 3;
            const int cia = 16 * q2 + 8 * s + 2 * pq2;
            const int gh  = h0 - 1 + r;
            const int gw  = w0 - 1 + (ce ? 65 : 0);
            float u0 = 0.f, u1 = 0.f;
            if (((unsigned)gh < (unsigned)HH) && ((unsigned)gw < (unsigned)WW)) {
                u0 = __ldg(Xb + (size_t)cia * HW + gh * WW + gw);
                u1 = __ldg(Xb + (size_t)(cia + 1) * HW + gh * WW + gw);
            }
            xs32[q2 * QS_ + pq2 * PPS_ + r * RS_ + 2 + 130 * ce + s] =
                pack_h2(u0, u1);
        }
    }
    __syncthreads();

    // per-warp A base (uint2 units): pq = lane&3, col = lane>>2, row = pxg
    const uint2* xw2 = (const uint2*)xs32 + (size_t)(lane & 3) * (PPS_ / 2)
                     + pxg * (RS_ / 2) + 1 + (lane >> 2);

#pragma unroll 1
    for (int kh = 0; kh < 3; kh++) {
#pragma unroll 1
        for (int kw = 0; kw < 3; kw++) {
            const uint2* abase = xw2 + kh * (RS_ / 2) + kw;

#pragma unroll
            for (int q = 0; q < 4; q++) {        // k16 chunk
                const uint4 bs0 = __ldg(bp);          // n-tiles 0,1
                const uint4 bs1 = __ldg(bp + 32);     // n-tiles 2,3
                bp += 128;

                const uint2* ap = abase + (size_t)q * (QS_ / 2);
                uint32_t a[4][4];
#pragma unroll
                for (int mt = 0; mt < 4; mt++) {
                    const uint2 lo = ap[mt * 16];        // (a0, a2)
                    const uint2 hi = ap[mt * 16 + 8];    // (a1, a3)
                    a[mt][0] = lo.x; a[mt][1] = hi.x;
                    a[mt][2] = lo.y; a[mt][3] = hi.y;
                }

#pragma unroll
                for (int mt = 0; mt < 4; mt++) {
                    MMA_F16(acc[mt][0], a[mt], bs0.x, bs0.y);
                    MMA_F16(acc[mt][1], a[mt], bs0.z, bs0.w);
                    MMA_F16(acc[mt][2], a[mt], bs1.x, bs1.y);
                    MMA_F16(acc[mt][3], a[mt], bs1.z, bs1.w);
                }
            }
        }
    }

    // ---- epilogue: streaming stores (evict-first; output is write-once) ----
    const int co0 = coh * 32;
    const int h   = h0 + pxg;
#pragma unroll
    for (int mt = 0; mt < 4; mt++) {
        const int wcol = w0 + mt * 16 + (lane >> 2);
        float* o0 = out + (size_t)b * COUT_ * HW + (size_t)h * WW + wcol;
#pragma unroll
        for (int nt = 0; nt < 4; nt++) {
            const int co = co0 + nt * 8 + 2 * (lane & 3);
            float* p = o0 + (size_t)co * HW;
            stg_cs(p,          acc[mt][nt][0]);   // (px,    co)
            stg_cs(p + HW,     acc[mt][nt][1]);   // (px,    co+1)
            stg_cs(p + 8,      acc[mt][nt][2]);   // (px+8,  co)
            stg_cs(p + HW + 8, acc[mt][nt][3]);   // (px+8,  co+1)
        }
    }
}

// ---------------------------------------------------------------------------
extern "C" void kernel_launch(void* const* d_in, const int* in_sizes, int n_in,
                              void* d_out, int out_size) {
    const float* X = (const float*)d_in[0];      // (16,64,256,256)
    const float* y = (const float*)d_in[1];      // (16,64)
    const float* w = (const float*)d_in[2];      // (64,64,3,3)
    float* out = (float*)d_out;                  // (16,64,256,256)

    __half* wt;
    cudaGetSymbolAddress((void**)&wt, g_wt);

    cudaFuncSetAttribute(conv_mma_kernel,
                         cudaFuncAttributeMaxDynamicSharedMemorySize, DYN_SMEM);

    modw_kernel<<<dim3(COUT_, B_), CIN_>>>(w, y, wt);

    dim3 grid(WW / 64, HH / 2, B_);
    conv_mma_kernel<<<grid, 128, DYN_SMEM>>>(X, wt, out);
}